// round 1
// baseline (speedup 1.0000x reference)
#include <cuda_runtime.h>
#include <math.h>

#define NN 100000
#define NE 3200000

// ---------------- scratch (device globals; no allocation allowed) ----------
__device__ float g_tmp[NN * 16];   // per-layer transformed features (row stride 16)
__device__ float g_agg[NN * 16];   // per-layer aggregation target (row stride 16)
__device__ int   g_src[NE];
__device__ int   g_dst[NE];
__device__ int   g_is64;

// ---------------- vector reductions (sm_90+) -------------------------------
__device__ __forceinline__ void red4(float* p, float a, float b, float c, float d) {
    asm volatile("red.global.add.v4.f32 [%0], {%1,%2,%3,%4};"
                 :: "l"(p), "f"(a), "f"(b), "f"(c), "f"(d) : "memory");
}
__device__ __forceinline__ void red2(float* p, float a, float b) {
    asm volatile("red.global.add.v2.f32 [%0], {%1,%2};"
                 :: "l"(p), "f"(a), "f"(b) : "memory");
}

// ---------------- detect int64 vs int32 edge_index -------------------------
// int64 indices < 100000 -> every odd 32-bit word (high half) is zero.
// int32 random indices -> essentially impossible that 256 words are all zero.
__global__ void detect_kernel(const unsigned int* __restrict__ w) {
    unsigned v = w[threadIdx.x * 2 + 1];
    int any = __syncthreads_or(v != 0u);
    if (threadIdx.x == 0) g_is64 = any ? 0 : 1;
}

__global__ void convert_kernel(const void* __restrict__ edge_index) {
    int e = blockIdx.x * blockDim.x + threadIdx.x;
    if (e >= NE) return;
    if (g_is64) {
        const long long* p = (const long long*)edge_index;
        g_src[e] = (int)p[e];
        g_dst[e] = (int)p[NE + e];
    } else {
        const int* p = (const int*)edge_index;
        g_src[e] = p[e];
        g_dst[e] = p[NE + e];
    }
}

// ---------------- layer-1 transform: tmp = x @ W1 (512 -> 8) ---------------
// Block = 128 threads = 128 nodes. k-chunked shared staging of x (coalesced
// global loads), padded rows (68 floats) for conflict-free LDS.128 reads,
// W1 broadcast through L1 (__ldg, all lanes same address).
// Also zeroes this node's g_agg row for the upcoming edge pass.
__global__ void l1_kernel(const float* __restrict__ x, const float* __restrict__ W1) {
    __shared__ float xs[128 * 68];
    const int tid = threadIdx.x;
    const int nb = blockIdx.x * 128;
    const int n = nb + tid;

    float acc[8];
#pragma unroll
    for (int j = 0; j < 8; j++) acc[j] = 0.f;

    for (int kc = 0; kc < 8; kc++) {
        // stage x[nb..nb+127][kc*64 .. kc*64+63] into shared
#pragma unroll
        for (int it = 0; it < 16; it++) {
            int idx = tid + it * 128;          // 0..2047
            int row = idx >> 4;                // node within block
            int c   = idx & 15;                // float4 within 64-float chunk
            int node = nb + row;
            float4 v = make_float4(0.f, 0.f, 0.f, 0.f);
            if (node < NN)
                v = __ldg((const float4*)(x + (size_t)node * 512 + kc * 64) + c);
            *(float4*)(&xs[row * 68 + c * 4]) = v;
        }
        __syncthreads();

        if (n < NN) {
#pragma unroll
            for (int k4 = 0; k4 < 16; k4++) {
                float4 xv = *(const float4*)(&xs[tid * 68 + k4 * 4]);
                float xa[4] = {xv.x, xv.y, xv.z, xv.w};
                int k = kc * 64 + k4 * 4;
#pragma unroll
                for (int r = 0; r < 4; r++) {
                    const float4* wp = (const float4*)(W1 + (size_t)(k + r) * 8);
                    float4 wA = __ldg(wp);
                    float4 wB = __ldg(wp + 1);
                    float xsv = xa[r];
                    acc[0] += xsv * wA.x; acc[1] += xsv * wA.y;
                    acc[2] += xsv * wA.z; acc[3] += xsv * wA.w;
                    acc[4] += xsv * wB.x; acc[5] += xsv * wB.y;
                    acc[6] += xsv * wB.z; acc[7] += xsv * wB.w;
                }
            }
        }
        __syncthreads();
    }

    if (n < NN) {
        float4* t = (float4*)(g_tmp + (size_t)n * 16);
        t[0] = make_float4(acc[0], acc[1], acc[2], acc[3]);
        t[1] = make_float4(acc[4], acc[5], acc[6], acc[7]);
        float4 z = make_float4(0.f, 0.f, 0.f, 0.f);
        float4* a = (float4*)(g_agg + (size_t)n * 16);
        a[0] = z; a[1] = z; a[2] = z; a[3] = z;
    }
}

// ---------------- edge scatter: agg[dst] += tmp[src] * w -------------------
// NV4 float4 chunks + optional float2 tail (F = 4*NV4 + 2*NV2).
template <int NV4, int NV2>
__global__ void edge_k(const float* __restrict__ w) {
    int e = blockIdx.x * blockDim.x + threadIdx.x;
    if (e >= NE) return;
    int s = g_src[e];
    int d = g_dst[e];
    float wt = w[e];
    const float4* ts = (const float4*)(g_tmp + (size_t)s * 16);
    float* ad = g_agg + (size_t)d * 16;
#pragma unroll
    for (int i = 0; i < NV4; i++) {
        float4 v = __ldg(&ts[i]);
        red4(ad + i * 4, v.x * wt, v.y * wt, v.z * wt, v.w * wt);
    }
    if (NV2) {
        float2 v = __ldg((const float2*)(g_tmp + (size_t)s * 16 + NV4 * 4));
        red2(ad + NV4 * 4, v.x * wt, v.y * wt);
    }
}

// ---------------- small transform: tmp = relu(agg + b_prev) @ W ------------
// One thread per node. Also zeroes this node's g_agg row after reading it.
template <int FIN, int FOUT>
__global__ void tsmall(const float* __restrict__ W, const float* __restrict__ b) {
    int n = blockIdx.x * blockDim.x + threadIdx.x;
    if (n >= NN) return;
    float h[FIN];
    float4* arow = (float4*)(g_agg + (size_t)n * 16);
#pragma unroll
    for (int i = 0; i < FIN / 4; i++) {
        float4 v = arow[i];
        h[i * 4 + 0] = fmaxf(v.x + __ldg(&b[i * 4 + 0]), 0.f);
        h[i * 4 + 1] = fmaxf(v.y + __ldg(&b[i * 4 + 1]), 0.f);
        h[i * 4 + 2] = fmaxf(v.z + __ldg(&b[i * 4 + 2]), 0.f);
        h[i * 4 + 3] = fmaxf(v.w + __ldg(&b[i * 4 + 3]), 0.f);
    }
    // zero agg row for next edge pass
    float4 z = make_float4(0.f, 0.f, 0.f, 0.f);
    arow[0] = z; arow[1] = z; arow[2] = z; arow[3] = z;

    float acc[FOUT];
#pragma unroll
    for (int o = 0; o < FOUT; o++) acc[o] = 0.f;
#pragma unroll
    for (int j = 0; j < FIN; j++) {
        float hj = h[j];
#pragma unroll
        for (int o = 0; o < FOUT; o++)
            acc[o] += hj * __ldg(&W[j * FOUT + o]);
    }
    float* trow = g_tmp + (size_t)n * 16;
#pragma unroll
    for (int o = 0; o < FOUT; o++) trow[o] = acc[o];
}

// ---------------- final: out = log_softmax(agg + b4) -----------------------
__global__ void lsm_kernel(const float* __restrict__ b4, float* __restrict__ out) {
    int n = blockIdx.x * blockDim.x + threadIdx.x;
    if (n >= NN) return;
    float v[10];
    float m = -1e30f;
#pragma unroll
    for (int i = 0; i < 10; i++) {
        v[i] = g_agg[(size_t)n * 16 + i] + __ldg(&b4[i]);
        m = fmaxf(m, v[i]);
    }
    float s = 0.f;
#pragma unroll
    for (int i = 0; i < 10; i++) s += expf(v[i] - m);
    float l = logf(s);
#pragma unroll
    for (int i = 0; i < 10; i++) out[(size_t)n * 10 + i] = v[i] - m - l;
}

// ---------------- launch ---------------------------------------------------
extern "C" void kernel_launch(void* const* d_in, const int* in_sizes, int n_in,
                              void* d_out, int out_size) {
    const float* x  = (const float*)d_in[0];
    const void*  ei = d_in[1];
    const float* ew = (const float*)d_in[2];
    const float* W1 = (const float*)d_in[3];
    const float* b1 = (const float*)d_in[4];
    const float* W2 = (const float*)d_in[5];
    const float* b2 = (const float*)d_in[6];
    const float* W3 = (const float*)d_in[7];
    const float* b3 = (const float*)d_in[8];
    const float* W4 = (const float*)d_in[9];
    const float* b4 = (const float*)d_in[10];
    float* out = (float*)d_out;

    const int EBLK = (NE + 255) / 256;
    const int NBLK = (NN + 255) / 256;

    detect_kernel<<<1, 256>>>((const unsigned int*)ei);
    convert_kernel<<<EBLK, 256>>>(ei);

    // layer 1: 512 -> 8
    l1_kernel<<<(NN + 127) / 128, 128>>>(x, W1);
    edge_k<2, 0><<<EBLK, 256>>>(ew);

    // layer 2: 8 -> 16 (relu(agg+b1) @ W2)
    tsmall<8, 16><<<NBLK, 256>>>(W2, b1);
    edge_k<4, 0><<<EBLK, 256>>>(ew);

    // layer 3: 16 -> 8
    tsmall<16, 8><<<NBLK, 256>>>(W3, b2);
    edge_k<2, 0><<<EBLK, 256>>>(ew);

    // layer 4: 8 -> 10
    tsmall<8, 10><<<NBLK, 256>>>(W4, b3);
    edge_k<2, 1><<<EBLK, 256>>>(ew);

    // log_softmax epilogue
    lsm_kernel<<<NBLK, 256>>>(b4, out);
}

// round 2
// speedup vs baseline: 1.6547x; 1.6547x over previous
#include <cuda_runtime.h>
#include <math.h>

#define NN 100000
#define NE 3200000

// ---------------- scratch (device globals; no allocation allowed) ----------
__device__ float g_tmp[NN * 8];    // per-layer features entering the edge pass
__device__ float g_agg[NN * 8];    // aggregation target (always 8-wide now)
__device__ int2  g_edge[NE];       // packed {src, dst}
__device__ int   g_is64;

// ---------------- vector reduction (sm_90+) --------------------------------
__device__ __forceinline__ void red4(float* p, float a, float b, float c, float d) {
    asm volatile("red.global.add.v4.f32 [%0], {%1,%2,%3,%4};"
                 :: "l"(p), "f"(a), "f"(b), "f"(c), "f"(d) : "memory");
}

// ---------------- detect int64 vs int32 edge_index -------------------------
__global__ void detect_kernel(const unsigned int* __restrict__ w) {
    unsigned v = w[threadIdx.x * 2 + 1];
    int any = __syncthreads_or(v != 0u);
    if (threadIdx.x == 0) g_is64 = any ? 0 : 1;
}

__global__ void convert_kernel(const void* __restrict__ edge_index) {
    int e = blockIdx.x * blockDim.x + threadIdx.x;
    if (e >= NE) return;
    int s, d;
    if (g_is64) {
        const long long* p = (const long long*)edge_index;
        s = (int)p[e];
        d = (int)p[NE + e];
    } else {
        const int* p = (const int*)edge_index;
        s = p[e];
        d = p[NE + e];
    }
    g_edge[e] = make_int2(s, d);
}

// ---------------- layer-1 transform: tmp = x @ W1 (512 -> 8) ---------------
// W1 staged in shared (16KB, LDS broadcast). x staged in shared in 64-float
// chunks (coalesced global loads, 68-float padded rows -> conflict-free).
// Zeroes this node's g_agg row for the upcoming edge pass.
__global__ void l1_kernel(const float* __restrict__ x, const float* __restrict__ W1) {
    __shared__ float ws[512 * 8];     // 16 KB
    __shared__ float xs[128 * 68];    // ~34.8 KB
    const int tid = threadIdx.x;
    const int nb = blockIdx.x * 128;
    const int n = nb + tid;

    // stage W1: 4096 floats, 128 threads -> 8 float4 each, coalesced
#pragma unroll
    for (int i = 0; i < 8; i++)
        ((float4*)ws)[tid + i * 128] = __ldg(((const float4*)W1) + tid + i * 128);
    __syncthreads();

    float acc[8];
#pragma unroll
    for (int j = 0; j < 8; j++) acc[j] = 0.f;

    for (int kc = 0; kc < 8; kc++) {
        // stage x[nb..nb+127][kc*64 .. kc*64+63]
#pragma unroll
        for (int it = 0; it < 16; it++) {
            int idx = tid + it * 128;
            int row = idx >> 4;
            int c   = idx & 15;
            int node = nb + row;
            float4 v = make_float4(0.f, 0.f, 0.f, 0.f);
            if (node < NN)
                v = __ldg((const float4*)(x + (size_t)node * 512 + kc * 64) + c);
            *(float4*)(&xs[row * 68 + c * 4]) = v;
        }
        __syncthreads();

        if (n < NN) {
#pragma unroll
            for (int k4 = 0; k4 < 16; k4++) {
                float4 xv = *(const float4*)(&xs[tid * 68 + k4 * 4]);
                float xa[4] = {xv.x, xv.y, xv.z, xv.w};
                int k = kc * 64 + k4 * 4;
#pragma unroll
                for (int r = 0; r < 4; r++) {
                    float4 wA = *(const float4*)(&ws[(k + r) * 8]);
                    float4 wB = *(const float4*)(&ws[(k + r) * 8 + 4]);
                    float xsv = xa[r];
                    acc[0] += xsv * wA.x; acc[1] += xsv * wA.y;
                    acc[2] += xsv * wA.z; acc[3] += xsv * wA.w;
                    acc[4] += xsv * wB.x; acc[5] += xsv * wB.y;
                    acc[6] += xsv * wB.z; acc[7] += xsv * wB.w;
                }
            }
        }
        __syncthreads();
    }

    if (n < NN) {
        float4* t = (float4*)(g_tmp + (size_t)n * 8);
        t[0] = make_float4(acc[0], acc[1], acc[2], acc[3]);
        t[1] = make_float4(acc[4], acc[5], acc[6], acc[7]);
        float4 z = make_float4(0.f, 0.f, 0.f, 0.f);
        float4* a = (float4*)(g_agg + (size_t)n * 8);
        a[0] = z; a[1] = z;
    }
}

// ---------------- edge scatter (always 8-wide): agg[dst] += tmp[src] * w ---
__global__ void edge_k(const float* __restrict__ w) {
    int e = blockIdx.x * blockDim.x + threadIdx.x;
    if (e >= NE) return;
    int2 sd = g_edge[e];
    float wt = w[e];
    const float4* ts = (const float4*)(g_tmp + (size_t)sd.x * 8);
    float* ad = g_agg + (size_t)sd.y * 8;
    float4 a = __ldg(ts);
    float4 b = __ldg(ts + 1);
    red4(ad,     a.x * wt, a.y * wt, a.z * wt, a.w * wt);
    red4(ad + 4, b.x * wt, b.y * wt, b.z * wt, b.w * wt);
}

// ---------------- elementwise: tmp = relu(agg + b), zero agg ---------------
__global__ void trelu(const float* __restrict__ b) {
    int n = blockIdx.x * blockDim.x + threadIdx.x;
    if (n >= NN) return;
    float4* arow = (float4*)(g_agg + (size_t)n * 8);
    float4* trow = (float4*)(g_tmp + (size_t)n * 8);
    float4 v0 = arow[0], v1 = arow[1];
    trow[0] = make_float4(fmaxf(v0.x + __ldg(&b[0]), 0.f),
                          fmaxf(v0.y + __ldg(&b[1]), 0.f),
                          fmaxf(v0.z + __ldg(&b[2]), 0.f),
                          fmaxf(v0.w + __ldg(&b[3]), 0.f));
    trow[1] = make_float4(fmaxf(v1.x + __ldg(&b[4]), 0.f),
                          fmaxf(v1.y + __ldg(&b[5]), 0.f),
                          fmaxf(v1.z + __ldg(&b[6]), 0.f),
                          fmaxf(v1.w + __ldg(&b[7]), 0.f));
    float4 z = make_float4(0.f, 0.f, 0.f, 0.f);
    arow[0] = z; arow[1] = z;
}

// ---------------- fused mid: tmp = relu(agg@W2 + b2) @ W3, zero agg --------
// agg is 8-wide (= A@relu1). W2: 8x16, W3: 16x8. All weights via L1 broadcast.
__global__ void tmid(const float* __restrict__ W2, const float* __restrict__ b2,
                     const float* __restrict__ W3) {
    int n = blockIdx.x * blockDim.x + threadIdx.x;
    if (n >= NN) return;
    float4* arow = (float4*)(g_agg + (size_t)n * 8);
    float4 v0 = arow[0], v1 = arow[1];
    float h[8] = {v0.x, v0.y, v0.z, v0.w, v1.x, v1.y, v1.z, v1.w};
    float4 z = make_float4(0.f, 0.f, 0.f, 0.f);
    arow[0] = z; arow[1] = z;

    float m[16];
#pragma unroll
    for (int o = 0; o < 16; o++) m[o] = __ldg(&b2[o]);
#pragma unroll
    for (int j = 0; j < 8; j++) {
        float hj = h[j];
#pragma unroll
        for (int o = 0; o < 16; o++)
            m[o] += hj * __ldg(&W2[j * 16 + o]);
    }
#pragma unroll
    for (int o = 0; o < 16; o++) m[o] = fmaxf(m[o], 0.f);

    float acc[8];
#pragma unroll
    for (int o = 0; o < 8; o++) acc[o] = 0.f;
#pragma unroll
    for (int j = 0; j < 16; j++) {
        float mj = m[j];
#pragma unroll
        for (int o = 0; o < 8; o++)
            acc[o] += mj * __ldg(&W3[j * 8 + o]);
    }
    float4* trow = (float4*)(g_tmp + (size_t)n * 8);
    trow[0] = make_float4(acc[0], acc[1], acc[2], acc[3]);
    trow[1] = make_float4(acc[4], acc[5], acc[6], acc[7]);
}

// ---------------- final: out = log_softmax(agg@W4 + b4) --------------------
__global__ void lsm_kernel(const float* __restrict__ W4, const float* __restrict__ b4,
                           float* __restrict__ out) {
    int n = blockIdx.x * blockDim.x + threadIdx.x;
    if (n >= NN) return;
    const float4* arow = (const float4*)(g_agg + (size_t)n * 8);
    float4 v0 = __ldg(arow), v1 = __ldg(arow + 1);
    float h[8] = {v0.x, v0.y, v0.z, v0.w, v1.x, v1.y, v1.z, v1.w};

    float v[10];
#pragma unroll
    for (int o = 0; o < 10; o++) v[o] = __ldg(&b4[o]);
#pragma unroll
    for (int j = 0; j < 8; j++) {
        float hj = h[j];
#pragma unroll
        for (int o = 0; o < 10; o++)
            v[o] += hj * __ldg(&W4[j * 10 + o]);
    }
    float m = -1e30f;
#pragma unroll
    for (int o = 0; o < 10; o++) m = fmaxf(m, v[o]);
    float s = 0.f;
#pragma unroll
    for (int o = 0; o < 10; o++) s += expf(v[o] - m);
    float l = logf(s);
#pragma unroll
    for (int o = 0; o < 10; o++) out[(size_t)n * 10 + o] = v[o] - m - l;
}

// ---------------- launch ---------------------------------------------------
extern "C" void kernel_launch(void* const* d_in, const int* in_sizes, int n_in,
                              void* d_out, int out_size) {
    const float* x  = (const float*)d_in[0];
    const void*  ei = d_in[1];
    const float* ew = (const float*)d_in[2];
    const float* W1 = (const float*)d_in[3];
    const float* b1 = (const float*)d_in[4];
    const float* W2 = (const float*)d_in[5];
    const float* b2 = (const float*)d_in[6];
    const float* W3 = (const float*)d_in[7];
    const float* b3 = (const float*)d_in[8];
    const float* W4 = (const float*)d_in[9];
    const float* b4 = (const float*)d_in[10];
    float* out = (float*)d_out;

    const int EBLK = (NE + 255) / 256;
    const int NBLK = (NN + 255) / 256;

    detect_kernel<<<1, 256>>>((const unsigned int*)ei);
    convert_kernel<<<EBLK, 256>>>(ei);

    // layer 1: tmp = x @ W1 (8-wide), agg zeroed
    l1_kernel<<<(NN + 127) / 128, 128>>>(x, W1);
    edge_k<<<EBLK, 256>>>(ew);            // agg1 = A @ (x W1)

    // layer 2 (reassociated): aggregate relu1 first, apply W2 later (fused into tmid)
    trelu<<<NBLK, 256>>>(b1);             // tmp = relu(agg1 + b1)
    edge_k<<<EBLK, 256>>>(ew);            // agg2 = A @ relu1

    // layer 3: tmp = relu(agg2 @ W2 + b2) @ W3  (fused 8->16->8)
    tmid<<<NBLK, 256>>>(W2, b2, W3);
    edge_k<<<EBLK, 256>>>(ew);            // agg3 = A @ (relu2 W3)

    // layer 4 (reassociated): aggregate relu3, apply W4 in the epilogue
    trelu<<<NBLK, 256>>>(b3);             // tmp = relu(agg3 + b3)
    edge_k<<<EBLK, 256>>>(ew);            // agg4 = A @ relu3

    lsm_kernel<<<NBLK, 256>>>(W4, b4, out);
}